// round 13
// baseline (speedup 1.0000x reference)
#include <cuda_runtime.h>
#include <cstdint>

#define TPB 128
#define NF 10
#define NC 64
#define NCOL 192
#define DK 5
#define INV_SQRT5 0.44721359549995793f

typedef uint32_t u32;

// smem strides (floats), chosen for conflict-free fragment access:
//  sA stride 136: bank = (8*(k%...)+p)%32 -> A-frag loads hit 32 distinct banks
//  sB stride 68:  bank = (4n+k)%32       -> B-frag loads hit 32 distinct banks
#define SA_STR 136
#define SB_STR 68
#define SW_STR 132

__device__ float g_K[NC * 8];   // K = posenc(centroids) @ Wk^T, stride 8

// ---------------------------------------------------------------------------
__global__ void precompute_K_kernel(const float* __restrict__ Wk,
                                    const float* __restrict__ centroids) {
    int c = threadIdx.x;
    if (c >= NC) return;
    float x0 = centroids[c * 3 + 0];
    float x1 = centroids[c * 3 + 1];
    float x2 = centroids[c * 3 + 2];
    float enc[60];
#pragma unroll
    for (int l = 0; l < NF; l++) {
        float f = (float)(1u << l);
        float s, co;
        sincosf(x0 * f, &s, &co); enc[l * 6 + 0] = s; enc[l * 6 + 3] = co;
        sincosf(x1 * f, &s, &co); enc[l * 6 + 1] = s; enc[l * 6 + 4] = co;
        sincosf(x2 * f, &s, &co); enc[l * 6 + 2] = s; enc[l * 6 + 5] = co;
    }
#pragma unroll
    for (int k = 0; k < 8; k++) {
        float a = 0.f;
        if (k < DK) {
#pragma unroll
            for (int e = 0; e < 60; e++) a += enc[e] * Wk[k * 60 + e];
        }
        g_K[c * 8 + k] = a;
    }
}

// ---------------------------------------------------------------------------
static __device__ __forceinline__ u32 to_tf32(float v) {
    u32 r;
    asm("cvt.rna.tf32.f32 %0, %1;" : "=r"(r) : "f"(v));
    return r;
}

static __device__ __forceinline__ void mma_tf32(float d[4], const u32 a[4],
                                                u32 b0, u32 b1) {
    asm volatile(
        "mma.sync.aligned.m16n8k8.row.col.f32.tf32.tf32.f32 "
        "{%0,%1,%2,%3}, {%4,%5,%6,%7}, {%8,%9}, {%0,%1,%2,%3};"
        : "+f"(d[0]), "+f"(d[1]), "+f"(d[2]), "+f"(d[3])
        : "r"(a[0]), "r"(a[1]), "r"(a[2]), "r"(a[3]), "r"(b0), "r"(b1));
}

// ---------------------------------------------------------------------------
// Persistent kernel. Per 128-point tile:
//   rgb[128,192] = enc[128,64] @ LM[192,64]^T  via mma.sync tf32 (warp-tiled,
//   D stays in registers). Weighted softmax reduce fused in fragment space.
//   kmeans kept exact fp32 (it IS the main output; TRADEOFF = 1).
// ---------------------------------------------------------------------------
__global__ __launch_bounds__(TPB, 1) void csa_kernel(
    const float* __restrict__ X,
    const int*   __restrict__ cids,
    const float* __restrict__ LM,
    const float* __restrict__ Wq,
    const float* __restrict__ Wv,
    float* __restrict__ out,
    int N, int mode)
{
    extern __shared__ float sm[];
    float* sA  = sm;                       // [64][136] tf32 enc   (8704 f)
    float* sB  = sA + 64 * SA_STR;         // [192][68] tf32 LM    (13056 f)
    float* sW  = sB + NCOL * SB_STR;       // [64][132] raw exp(s) (8448 f)
    float* sLM = sW + NC * SW_STR;         // [192*60] exact fp32  (11520 f)
    float* sZ  = sLM + NCOL * 60;          // [132] 1/Z per point
    float* sK  = sZ + 132;                 // [64*8]
    float* sWq = sK + NC * 8;              // [304]
    float* sWv = sWq + 304;                // [16]

    int tid = threadIdx.x;

    // one-time loads
    for (int i = tid; i < NCOL * 64; i += TPB) {
        int n = i >> 6, k = i & 63;
        float v = (k < 60) ? LM[n * 60 + k] : 0.f;
        sB[n * SB_STR + k] = __uint_as_float(to_tf32(v));
    }
    for (int i = tid; i < NCOL * 60 / 4; i += TPB)
        ((float4*)sLM)[i] = ((const float4*)LM)[i];
    for (int i = tid; i < NC * 8; i += TPB) sK[i] = g_K[i];
    for (int i = tid; i < DK * 60; i += TPB) sWq[i] = Wq[i];
    if (tid < 9) sWv[tid] = Wv[tid];
    __syncthreads();

    const int lane = tid & 31;
    const int wbase = (tid >> 5) << 5;   // warp's 32 rows within tile
    const int g = lane >> 2, r4 = lane & 3;
    const int tiles = (N + 127) >> 7;

    for (int tile = blockIdx.x; tile < tiles; tile += gridDim.x) {
        int p = tile * 128 + tid;
        int pc = min(p, N - 1);

        // ---- prep: posenc (double-angle), q, km (exact), scores ----
        float enc[60];
        {
            float x0 = X[3 * pc], x1 = X[3 * pc + 1], x2 = X[3 * pc + 2];
            float s0, c0, s1, c1, s2, c2;
            sincosf(x0, &s0, &c0);
            sincosf(x1, &s1, &c1);
            sincosf(x2, &s2, &c2);
#pragma unroll
            for (int l = 0; l < NF; l++) {
                enc[l * 6 + 0] = s0; enc[l * 6 + 1] = s1; enc[l * 6 + 2] = s2;
                enc[l * 6 + 3] = c0; enc[l * 6 + 4] = c1; enc[l * 6 + 5] = c2;
                if (l < NF - 1) {
                    float t, u;
                    t = s0 * c0; u = fmaf(c0, c0, -0.5f); s0 = t + t; c0 = u + u;
                    t = s1 * c1; u = fmaf(c1, c1, -0.5f); s1 = t + t; c1 = u + u;
                    t = s2 * c2; u = fmaf(c2, c2, -0.5f); s2 = t + t; c2 = u + u;
                }
            }
        }

        float q[DK];
#pragma unroll
        for (int k = 0; k < DK; k++) {
            float a = 0.f;
            const float4* wp = (const float4*)(sWq + k * 60);
#pragma unroll
            for (int t = 0; t < 15; t++) {
                float4 w4 = wp[t];
                a += w4.x * enc[4 * t] + w4.y * enc[4 * t + 1]
                   + w4.z * enc[4 * t + 2] + w4.w * enc[4 * t + 3];
            }
            q[k] = a * INV_SQRT5;
        }

        int cid = cids[pc];
        float km0 = 0.f, km1 = 0.f, km2 = 0.f;
        {
            const float4* rp = (const float4*)(sLM + 3 * cid * 60);
#pragma unroll
            for (int t = 0; t < 15; t++) {
                float4 a = rp[t], b = rp[15 + t], c4 = rp[30 + t];
                float e0 = enc[4 * t], e1 = enc[4 * t + 1];
                float e2 = enc[4 * t + 2], e3 = enc[4 * t + 3];
                km0 += a.x  * e0 + a.y  * e1 + a.z  * e2 + a.w  * e3;
                km1 += b.x  * e0 + b.y  * e1 + b.z  * e2 + b.w  * e3;
                km2 += c4.x * e0 + c4.y * e1 + c4.z * e2 + c4.w * e3;
            }
        }

        float Z = 0.f;
#pragma unroll
        for (int c = 0; c < NC; c++) {
            float4 k4 = *(const float4*)(sK + c * 8);
            float k5 = sK[c * 8 + 4];
            float s = q[0] * k4.x + q[1] * k4.y + q[2] * k4.z + q[3] * k4.w
                    + q[4] * k5;
            float w = __expf(s);
            Z += w;
            sW[c * SW_STR + tid] = w;
        }
        sZ[tid] = 1.0f / Z;

        // stage enc (tf32) into sA, [k][point]
#pragma unroll
        for (int k = 0; k < 60; k++)
            sA[k * SA_STR + tid] = __uint_as_float(to_tf32(enc[k]));
#pragma unroll
        for (int k = 60; k < 64; k++) sA[k * SA_STR + tid] = 0.f;
        __syncthreads();

        // ---- warp GEMM + fused weighted reduce ----
        // preload all A fragments (this warp's 32 rows x K=64)
        u32 af[2][8][4];
#pragma unroll
        for (int mt = 0; mt < 2; mt++) {
#pragma unroll
            for (int ks = 0; ks < 8; ks++) {
                int rr = wbase + mt * 16 + g;
                int kk = ks * 8 + r4;
                af[mt][ks][0] = __float_as_uint(sA[kk * SA_STR + rr]);
                af[mt][ks][1] = __float_as_uint(sA[kk * SA_STR + rr + 8]);
                af[mt][ks][2] = __float_as_uint(sA[(kk + 4) * SA_STR + rr]);
                af[mt][ks][3] = __float_as_uint(sA[(kk + 4) * SA_STR + rr + 8]);
            }
        }

        float p00 = 0.f, p01 = 0.f, p02 = 0.f;   // slot 0 (mt0, rows g)
        float p10 = 0.f, p11 = 0.f, p12 = 0.f;   // slot 1 (mt0, rows g+8)
        float p20 = 0.f, p21 = 0.f, p22 = 0.f;   // slot 2 (mt1, rows g+16)
        float p30 = 0.f, p31 = 0.f, p32 = 0.f;   // slot 3 (mt1, rows g+24)

        for (int nt = 0; nt < 24; nt++) {
            float d0[4] = {0.f, 0.f, 0.f, 0.f};
            float d1[4] = {0.f, 0.f, 0.f, 0.f};
            const float* bp = sB + (nt * 8 + g) * SB_STR;
#pragma unroll
            for (int ks = 0; ks < 8; ks++) {
                u32 b0 = __float_as_uint(bp[ks * 8 + r4]);
                u32 b1 = __float_as_uint(bp[ks * 8 + r4 + 4]);
                mma_tf32(d0, af[0][ks], b0, b1);
                mma_tf32(d1, af[1][ks], b0, b1);
            }
#pragma unroll
            for (int mt = 0; mt < 2; mt++) {
#pragma unroll
                for (int e = 0; e < 4; e++) {
                    int col = nt * 8 + 2 * r4 + (e & 1);
                    int c = col / 3;
                    int j = col - 3 * c;
                    int prow = wbase + mt * 16 + 8 * (e >> 1) + g;
                    float wv = sW[c * SW_STR + prow];
                    float v = (mt ? d1[e] : d0[e]) * wv;
                    if (mt == 0 && (e >> 1) == 0) {
                        if (j == 0) p00 += v; else if (j == 1) p01 += v; else p02 += v;
                    } else if (mt == 0) {
                        if (j == 0) p10 += v; else if (j == 1) p11 += v; else p12 += v;
                    } else if ((e >> 1) == 0) {
                        if (j == 0) p20 += v; else if (j == 1) p21 += v; else p22 += v;
                    } else {
                        if (j == 0) p30 += v; else if (j == 1) p31 += v; else p32 += v;
                    }
                }
            }
        }

        // butterfly-reduce over the 4 lanes sharing each row group
#pragma unroll
        for (int s = 1; s <= 2; s <<= 1) {
            p00 += __shfl_xor_sync(0xffffffffu, p00, s);
            p01 += __shfl_xor_sync(0xffffffffu, p01, s);
            p02 += __shfl_xor_sync(0xffffffffu, p02, s);
            p10 += __shfl_xor_sync(0xffffffffu, p10, s);
            p11 += __shfl_xor_sync(0xffffffffu, p11, s);
            p12 += __shfl_xor_sync(0xffffffffu, p12, s);
            p20 += __shfl_xor_sync(0xffffffffu, p20, s);
            p21 += __shfl_xor_sync(0xffffffffu, p21, s);
            p22 += __shfl_xor_sync(0xffffffffu, p22, s);
            p30 += __shfl_xor_sync(0xffffffffu, p30, s);
            p31 += __shfl_xor_sync(0xffffffffu, p31, s);
            p32 += __shfl_xor_sync(0xffffffffu, p32, s);
        }

        // owner thread writes main out (= kmeans, TRADEOFF = 1) and kmeans
        if (p < N) {
            out[3 * p + 0] = km0;
            out[3 * p + 1] = km1;
            out[3 * p + 2] = km2;
            if (mode == 3) {
                float* kmp = out + 3 * (size_t)N;
                kmp[3 * p + 0] = km0;
                kmp[3 * p + 1] = km1;
                kmp[3 * p + 2] = km2;
            }
        }
        // reducer lane (lane%4 == slot) writes attention for its row
        if (mode == 3) {
            int s = r4;
            int prow = wbase + 16 * (s >> 1) + 8 * (s & 1) + g;
            int pp = tile * 128 + prow;
            if (pp < N) {
                float a0, a1, a2;
                if (s == 0)      { a0 = p00; a1 = p01; a2 = p02; }
                else if (s == 1) { a0 = p10; a1 = p11; a2 = p12; }
                else if (s == 2) { a0 = p20; a1 = p21; a2 = p22; }
                else             { a0 = p30; a1 = p31; a2 = p32; }
                float iz = sZ[prow];
                float t0 = a0 * iz, t1 = a1 * iz, t2 = a2 * iz;
                float* atp = out + 6 * (size_t)N;
                atp[3 * pp + 0] = sWv[0] * t0 + sWv[1] * t1 + sWv[2] * t2;
                atp[3 * pp + 1] = sWv[3] * t0 + sWv[4] * t1 + sWv[5] * t2;
                atp[3 * pp + 2] = sWv[6] * t0 + sWv[7] * t1 + sWv[8] * t2;
            }
        }
        __syncthreads();   // protect sA/sW/sZ before next tile's prep
    }
}

extern "C" void kernel_launch(void* const* d_in, const int* in_sizes, int n_in,
                              void* d_out, int out_size) {
    const float* X         = (const float*)d_in[0];
    const int*   cids      = (const int*)  d_in[1];
    const float* LM        = (const float*)d_in[2];
    const float* Wq        = (const float*)d_in[3];
    const float* Wk        = (const float*)d_in[4];
    const float* Wv        = (const float*)d_in[5];
    const float* centroids = (const float*)d_in[6];

    int N = in_sizes[0] / 3;
    int mode = (out_size >= 9 * N) ? 3 : 1;

    // floats: sA 8704 + sB 13056 + sW 8448 + sLM 11520 + sZ 132 + sK 512
    //       + sWq 304 + sWv 16 = 42692 -> 170768 bytes
    const int SMEM = 42692 * 4;
    cudaFuncSetAttribute(csa_kernel,
                         cudaFuncAttributeMaxDynamicSharedMemorySize, SMEM);

    precompute_K_kernel<<<1, 64>>>(Wk, centroids);
    csa_kernel<<<148, TPB, SMEM>>>(X, cids, LM, Wq, Wv, (float*)d_out, N, mode);
}

// round 14
// speedup vs baseline: 3.0977x; 3.0977x over previous
#include <cuda_runtime.h>
#include <cstdint>

#define TPB 256
#define TILE 256
#define NF 10
#define NC 64
#define NCOL 192
#define DK 5
#define INV_SQRT5 0.44721359549995793f

typedef uint32_t u32;

#define SA_STR 136   // A staging stride: af loads hit 32 distinct banks
#define SB_STR 68    // B stride: B-frag loads hit 32 distinct banks
#define SD_STR 35    // D-chunk stride: readback conflict-free (gcd(3,32)=1)

__device__ float g_K[NC * 8];   // K = posenc(centroids) @ Wk^T, stride 8

// ---------------------------------------------------------------------------
__global__ void precompute_K_kernel(const float* __restrict__ Wk,
                                    const float* __restrict__ centroids) {
    int c = threadIdx.x;
    if (c >= NC) return;
    float x0 = centroids[c * 3 + 0];
    float x1 = centroids[c * 3 + 1];
    float x2 = centroids[c * 3 + 2];
    float enc[60];
#pragma unroll
    for (int l = 0; l < NF; l++) {
        float f = (float)(1u << l);
        float s, co;
        sincosf(x0 * f, &s, &co); enc[l * 6 + 0] = s; enc[l * 6 + 3] = co;
        sincosf(x1 * f, &s, &co); enc[l * 6 + 1] = s; enc[l * 6 + 4] = co;
        sincosf(x2 * f, &s, &co); enc[l * 6 + 2] = s; enc[l * 6 + 5] = co;
    }
#pragma unroll
    for (int k = 0; k < 8; k++) {
        float a = 0.f;
        if (k < DK) {
#pragma unroll
            for (int e = 0; e < 60; e++) a += enc[e] * Wk[k * 60 + e];
        }
        g_K[c * 8 + k] = a;
    }
}

// ---------------------------------------------------------------------------
static __device__ __forceinline__ u32 to_tf32(float v) {
    u32 r;
    asm("cvt.rna.tf32.f32 %0, %1;" : "=r"(r) : "f"(v));
    return r;
}

static __device__ __forceinline__ void mma_tf32(float d[4], const u32 a[4],
                                                u32 b0, u32 b1) {
    asm volatile(
        "mma.sync.aligned.m16n8k8.row.col.f32.tf32.tf32.f32 "
        "{%0,%1,%2,%3}, {%4,%5,%6,%7}, {%8,%9}, {%0,%1,%2,%3};"
        : "+f"(d[0]), "+f"(d[1]), "+f"(d[2]), "+f"(d[3])
        : "r"(a[0]), "r"(a[1]), "r"(a[2]), "r"(a[3]), "r"(b0), "r"(b1));
}

// identical score formula everywhere (Z pass and reduce recompute)
static __device__ __forceinline__ float cluster_w(const float* sK,
                                                  const float q[DK], int c) {
    float4 k4 = *(const float4*)(sK + c * 8);
    float  k5 = sK[c * 8 + 4];
    float s = q[0] * k4.x + q[1] * k4.y + q[2] * k4.z + q[3] * k4.w + q[4] * k5;
    return __expf(s);
}

// ---------------------------------------------------------------------------
// Persistent kernel, 256 threads / 256-point tiles, 2 CTAs/SM (4 warps/SMSP).
//   rgb[256,192] = enc_tf32[256,64] @ LM_tf32[192,64]^T via mma.sync tf32.
//   D staged to smem in 32-col chunks; each thread reduces its OWN row with
//   weights recomputed from its registers. kmeans exact fp32 via L2 reads.
// ---------------------------------------------------------------------------
__global__ __launch_bounds__(TPB, 2) void csa_kernel(
    const float* __restrict__ X,
    const int*   __restrict__ cids,
    const float* __restrict__ LM,
    const float* __restrict__ Wq,
    const float* __restrict__ Wv,
    float* __restrict__ out,
    int N, int mode)
{
    extern __shared__ float sm[];
    float* sB  = sm;                 // [192][68] tf32 LM          13056 f
    float* sU  = sB + NCOL * SB_STR; // union: A stage [64][136] /  8960 f
                                     //        D chunk [256][35]
    float* sK  = sU + 8960;          // [64*8]                       512 f
    float* sWq = sK + NC * 8;        // [304]
    float* sWv = sWq + 304;          // [16]

    const int tid = threadIdx.x;

    // one-time loads
    for (int i = tid; i < NCOL * 64; i += TPB) {
        int n = i >> 6, k = i & 63;
        float v = (k < 60) ? LM[n * 60 + k] : 0.f;
        sB[n * SB_STR + k] = __uint_as_float(to_tf32(v));
    }
    for (int i = tid; i < NC * 8; i += TPB) sK[i] = g_K[i];
    for (int i = tid; i < DK * 60; i += TPB) sWq[i] = Wq[i];
    if (tid < 9) sWv[tid] = Wv[tid];
    __syncthreads();

    const int lane = tid & 31;
    const int warp = tid >> 5;
    const int g = lane >> 2, r4 = lane & 3;
    const int half = tid >> 7;            // 0: warps 0-3, 1: warps 4-7
    const int rb = (warp & 3) * 32 + g;   // local row base within half buffer
    const int wrow = warp * 32 + g;       // tile-local row base for D staging
    const int tiles = (N + TILE - 1) / TILE;

    for (int tile = blockIdx.x; tile < tiles; tile += gridDim.x) {
        int p = tile * TILE + tid;
        int pc = min(p, N - 1);

        // ---- prep: posenc (double-angle), q, Z, exact kmeans via L2 ----
        float enc[64];
        {
            float x0 = X[3 * pc], x1 = X[3 * pc + 1], x2 = X[3 * pc + 2];
            float s0, c0, s1, c1, s2, c2;
            sincosf(x0, &s0, &c0);
            sincosf(x1, &s1, &c1);
            sincosf(x2, &s2, &c2);
#pragma unroll
            for (int l = 0; l < NF; l++) {
                enc[l * 6 + 0] = s0; enc[l * 6 + 1] = s1; enc[l * 6 + 2] = s2;
                enc[l * 6 + 3] = c0; enc[l * 6 + 4] = c1; enc[l * 6 + 5] = c2;
                if (l < NF - 1) {
                    float t, u;
                    t = s0 * c0; u = fmaf(c0, c0, -0.5f); s0 = t + t; c0 = u + u;
                    t = s1 * c1; u = fmaf(c1, c1, -0.5f); s1 = t + t; c1 = u + u;
                    t = s2 * c2; u = fmaf(c2, c2, -0.5f); s2 = t + t; c2 = u + u;
                }
            }
            enc[60] = enc[61] = enc[62] = enc[63] = 0.f;
        }

        float q[DK];
#pragma unroll
        for (int k = 0; k < DK; k++) {
            float a = 0.f;
            const float4* wp = (const float4*)(sWq + k * 60);
#pragma unroll
            for (int t = 0; t < 15; t++) {
                float4 w4 = wp[t];
                a += w4.x * enc[4 * t] + w4.y * enc[4 * t + 1]
                   + w4.z * enc[4 * t + 2] + w4.w * enc[4 * t + 3];
            }
            q[k] = a * INV_SQRT5;
        }

        float Z = 0.f;
#pragma unroll
        for (int c = 0; c < NC; c++) Z += cluster_w(sK, q, c);

        float km0 = 0.f, km1 = 0.f, km2 = 0.f;
        {
            const float4* rp = (const float4*)(LM + 3 * (size_t)cids[pc] * 60);
#pragma unroll
            for (int t = 0; t < 15; t++) {
                float4 a = __ldg(rp + t);
                float4 b = __ldg(rp + 15 + t);
                float4 c4 = __ldg(rp + 30 + t);
                float e0 = enc[4 * t], e1 = enc[4 * t + 1];
                float e2 = enc[4 * t + 2], e3 = enc[4 * t + 3];
                km0 += a.x  * e0 + a.y  * e1 + a.z  * e2 + a.w  * e3;
                km1 += b.x  * e0 + b.y  * e1 + b.z  * e2 + b.w  * e3;
                km2 += c4.x * e0 + c4.y * e1 + c4.z * e2 + c4.w * e3;
            }
        }

        // ---- two-phase A staging + fragment preload (branch-duplicated so
        //      enc and af never overlap in any path's live range) ----
        u32 af[2][8][4];
        if (half == 0) {
            int lrow = tid;
#pragma unroll
            for (int k = 0; k < 64; k++)
                sU[k * SA_STR + lrow] = __uint_as_float(to_tf32(enc[k]));
            __syncthreads();                                  // B1
#pragma unroll
            for (int ks = 0; ks < 8; ks++) {
                int kk = ks * 8 + r4;
                af[0][ks][0] = __float_as_uint(sU[kk * SA_STR + rb]);
                af[0][ks][1] = __float_as_uint(sU[kk * SA_STR + rb + 8]);
                af[0][ks][2] = __float_as_uint(sU[(kk + 4) * SA_STR + rb]);
                af[0][ks][3] = __float_as_uint(sU[(kk + 4) * SA_STR + rb + 8]);
                af[1][ks][0] = __float_as_uint(sU[kk * SA_STR + rb + 16]);
                af[1][ks][1] = __float_as_uint(sU[kk * SA_STR + rb + 24]);
                af[1][ks][2] = __float_as_uint(sU[(kk + 4) * SA_STR + rb + 16]);
                af[1][ks][3] = __float_as_uint(sU[(kk + 4) * SA_STR + rb + 24]);
            }
            __syncthreads();                                  // B2
            __syncthreads();                                  // B3
        } else {
            __syncthreads();                                  // B1
            __syncthreads();                                  // B2
            int lrow = tid - 128;
#pragma unroll
            for (int k = 0; k < 64; k++)
                sU[k * SA_STR + lrow] = __uint_as_float(to_tf32(enc[k]));
            __syncthreads();                                  // B3
#pragma unroll
            for (int ks = 0; ks < 8; ks++) {
                int kk = ks * 8 + r4;
                af[0][ks][0] = __float_as_uint(sU[kk * SA_STR + rb]);
                af[0][ks][1] = __float_as_uint(sU[kk * SA_STR + rb + 8]);
                af[0][ks][2] = __float_as_uint(sU[(kk + 4) * SA_STR + rb]);
                af[0][ks][3] = __float_as_uint(sU[(kk + 4) * SA_STR + rb + 8]);
                af[1][ks][0] = __float_as_uint(sU[kk * SA_STR + rb + 16]);
                af[1][ks][1] = __float_as_uint(sU[kk * SA_STR + rb + 24]);
                af[1][ks][2] = __float_as_uint(sU[(kk + 4) * SA_STR + rb + 16]);
                af[1][ks][3] = __float_as_uint(sU[(kk + 4) * SA_STR + rb + 24]);
            }
        }
        __syncthreads();                                      // B4: sU -> D chunk

        // ---- MMA + chunked own-row weighted reduce ----
        float acc0 = 0.f, acc1 = 0.f, acc2 = 0.f;
#pragma unroll
        for (int ct = 0; ct < 6; ct++) {
#pragma unroll
            for (int ntl = 0; ntl < 4; ntl++) {
                int nt = ct * 4 + ntl;
                float d0[4] = {0.f, 0.f, 0.f, 0.f};
                float d1[4] = {0.f, 0.f, 0.f, 0.f};
                const float* bp = sB + (nt * 8 + g) * SB_STR;
#pragma unroll
                for (int ks = 0; ks < 8; ks++) {
                    u32 b0 = __float_as_uint(bp[ks * 8 + r4]);
                    u32 b1 = __float_as_uint(bp[ks * 8 + r4 + 4]);
                    mma_tf32(d0, af[0][ks], b0, b1);
                    mma_tf32(d1, af[1][ks], b0, b1);
                }
#pragma unroll
                for (int e = 0; e < 4; e++) {
                    int col = ntl * 8 + 2 * r4 + (e & 1);
                    int ro = 8 * (e >> 1);
                    sU[(wrow + ro) * SD_STR + col]      = d0[e];
                    sU[(wrow + 16 + ro) * SD_STR + col] = d1[e];
                }
            }
            __syncthreads();     // chunk staged

            const float* drow = sU + tid * SD_STR;
            float w = 0.f;
            int cl = -1;
#pragma unroll
            for (int cc = 0; cc < 32; cc++) {
                int gc = ct * 32 + cc;
                int c = gc / 3, j = gc - 3 * c;
                if (c != cl) { w = cluster_w(sK, q, c); cl = c; }
                float v = drow[cc] * w;
                if (j == 0) acc0 += v;
                else if (j == 1) acc1 += v;
                else acc2 += v;
            }
            __syncthreads();     // chunk consumed (also guards next tile's stage)
        }

        // ---- outputs ----
        if (p < N) {
            // TRADEOFF = 1.0 -> main out == kmeans_rgb exactly
            out[3 * p + 0] = km0;
            out[3 * p + 1] = km1;
            out[3 * p + 2] = km2;
            if (mode == 3) {
                float invZ = 1.0f / Z;
                float t0 = acc0 * invZ, t1 = acc1 * invZ, t2 = acc2 * invZ;
                float* kmp = out + 3 * (size_t)N;
                float* atp = out + 6 * (size_t)N;
                kmp[3 * p + 0] = km0;
                kmp[3 * p + 1] = km1;
                kmp[3 * p + 2] = km2;
                atp[3 * p + 0] = sWv[0] * t0 + sWv[1] * t1 + sWv[2] * t2;
                atp[3 * p + 1] = sWv[3] * t0 + sWv[4] * t1 + sWv[5] * t2;
                atp[3 * p + 2] = sWv[6] * t0 + sWv[7] * t1 + sWv[8] * t2;
            }
        }
    }
}

extern "C" void kernel_launch(void* const* d_in, const int* in_sizes, int n_in,
                              void* d_out, int out_size) {
    const float* X         = (const float*)d_in[0];
    const int*   cids      = (const int*)  d_in[1];
    const float* LM        = (const float*)d_in[2];
    const float* Wq        = (const float*)d_in[3];
    const float* Wk        = (const float*)d_in[4];
    const float* Wv        = (const float*)d_in[5];
    const float* centroids = (const float*)d_in[6];

    int N = in_sizes[0] / 3;
    int mode = (out_size >= 9 * N) ? 3 : 1;

    // floats: sB 13056 + sU 8960 + sK 512 + sWq 304 + sWv 16 = 22848
    const int SMEM = 22848 * 4;   // 91392 B -> 2 CTAs/SM
    cudaFuncSetAttribute(csa_kernel,
                         cudaFuncAttributeMaxDynamicSharedMemorySize, SMEM);

    precompute_K_kernel<<<1, 64>>>(Wk, centroids);
    csa_kernel<<<296, TPB, SMEM>>>(X, cids, LM, Wq, Wv, (float*)d_out, N, mode);
}